// round 9
// baseline (speedup 1.0000x reference)
#include <cuda_runtime.h>
#include <cuda_fp16.h>
#include <cstdint>

#define NPTS 16384
#define MP   4096
#define KNB  16

// ---------------- helpers ----------------
__device__ __forceinline__ uint32_t s2u(const void* p) {
    uint32_t a;
    asm("{ .reg .u64 t; cvta.to.shared.u64 t, %1; cvt.u32.u64 %0, t; }" : "=r"(a) : "l"(p));
    return a;
}
#define CP16(dst, src) asm volatile("cp.async.cg.shared.global [%0], [%1], 16;" :: "r"(dst), "l"(src))
#define CP_COMMIT()    asm volatile("cp.async.commit_group;" ::: "memory")
#define CP_WAIT0()     asm volatile("cp.async.wait_group 0;" ::: "memory")
#define CP_WAIT1()     asm volatile("cp.async.wait_group 1;" ::: "memory")

// [128][128] f16 tile, 256B rows, 16B chunks XOR-swizzled by row
__device__ __forceinline__ uint32_t tile_off(int r, int c16) {
    return (uint32_t)(r * 256 + ((c16 ^ (r & 7)) << 4));
}
template <int NT>
__device__ __forceinline__ void fill_tile_async(uint32_t dst, const __half* __restrict__ src, int tid) {
#pragma unroll
    for (int it = 0; it < 2048 / NT; it++) {
        int idx = tid + it * NT;
        int r = idx >> 4, c16 = idx & 15;
        CP16(dst + tile_off(r, c16), src + r * 128 + c16 * 8);
    }
}
__device__ __forceinline__ void ldmA(uint32_t* a, uint32_t base, int mrow, int kcol, int lane) {
    uint32_t addr = base + tile_off(mrow + (lane & 15), (kcol >> 3) + (lane >> 4));
    asm volatile("ldmatrix.sync.aligned.m8n8.x4.shared.b16 {%0,%1,%2,%3}, [%4];"
        : "=r"(a[0]), "=r"(a[1]), "=r"(a[2]), "=r"(a[3]) : "r"(addr));
}
__device__ __forceinline__ void ldmB(uint32_t* b, uint32_t base, int ncol, int kcol, int lane) {
    uint32_t addr = base + tile_off(ncol + (lane & 7), (kcol >> 3) + ((lane >> 3) & 1));
    asm volatile("ldmatrix.sync.aligned.m8n8.x2.shared.b16 {%0,%1}, [%2];"
        : "=r"(b[0]), "=r"(b[1]) : "r"(addr));
}
__device__ __forceinline__ void mma16816(float* d, const uint32_t* a, const uint32_t* b) {
    asm volatile("mma.sync.aligned.m16n8k16.row.col.f32.f16.f16.f32 "
        "{%0,%1,%2,%3}, {%4,%5,%6,%7}, {%8,%9}, {%0,%1,%2,%3};"
        : "+f"(d[0]), "+f"(d[1]), "+f"(d[2]), "+f"(d[3])
        : "r"(a[0]), "r"(a[1]), "r"(a[2]), "r"(a[3]), "r"(b[0]), "r"(b[1]));
}
__device__ __forceinline__ float leaky_f(float v) { return v < 0.f ? 0.2f * v : v; }

// split-f16 3-product 128x128x128 tile for 8 warps: warp (wm,wn) owns 64x32
__device__ __forceinline__ void mma_core(uint32_t sA, uint32_t sB, int wm, int wn, int lane,
                                         float acc[4][4][4]) {
#pragma unroll 1
    for (int ks = 0; ks < 8; ks++) {
        const int kc = ks * 16;
        uint32_t ah[4][4], al[4][4], bh[4][2], bl[4][2];
#pragma unroll
        for (int mi = 0; mi < 4; mi++) {
            ldmA(ah[mi], sA, wm * 64 + mi * 16, kc, lane);
            ldmA(al[mi], sA + 32768, wm * 64 + mi * 16, kc, lane);
        }
#pragma unroll
        for (int ni = 0; ni < 4; ni++) {
            ldmB(bh[ni], sB, wn * 32 + ni * 8, kc, lane);
            ldmB(bl[ni], sB + 32768, wn * 32 + ni * 8, kc, lane);
        }
#pragma unroll
        for (int mi = 0; mi < 4; mi++)
#pragma unroll
            for (int ni = 0; ni < 4; ni++) {
                mma16816(acc[mi][ni], ah[mi], bh[ni]);
                mma16816(acc[mi][ni], ah[mi], bl[ni]);
                mma16816(acc[mi][ni], al[mi], bh[ni]);
            }
    }
}
#define ACC_ZERO4(acc) do { \
    _Pragma("unroll") for (int mi = 0; mi < 4; mi++) \
    _Pragma("unroll") for (int ni = 0; ni < 4; ni++) \
    _Pragma("unroll") for (int j = 0; j < 4; j++) acc[mi][ni][j] = 0.f; } while (0)

// ---------------- scratch ----------------
__device__ __half g_sh[81920 * 128], g_sl[81920 * 128];
__device__ __half g_w1h[128 * 128],  g_w1l[128 * 128];
__device__ __half g_w2h[1024 * 128], g_w2l[1024 * 128];
__device__ __half g_wlh[512 * 128],  g_wll[512 * 128];
__device__ __half g_wrh[512 * 128],  g_wrl[512 * 128];
__device__ float g_xn[65536];
__device__ float g_XLR[5 * 16384 * 512];
__device__ float g_gf[5 * 4 * 1024];
__device__ float g_attn[16];
__device__ int   g_nbr[4 * 16384 * 16];
__device__ float g_res[4 * 16384 * 128];

// ---------------- preludes ----------------
__global__ void zero_gf_kernel() {
    int i = blockIdx.x * 256 + threadIdx.x;
    if (i < 5 * 4 * 1024) g_gf[i] = 0.f;
}
__global__ void split_seq_kernel(const float* __restrict__ seq) {
    size_t i = (size_t)blockIdx.x * 256 + threadIdx.x;
    float4 v = ((const float4*)seq)[i];
    float x[4] = {v.x, v.y, v.z, v.w};
    unsigned short h[4], l[4];
#pragma unroll
    for (int j = 0; j < 4; j++) {
        __half hb = __float2half_rn(x[j]);
        h[j] = __half_as_ushort(hb);
        l[j] = __half_as_ushort(__float2half_rn(x[j] - __half2float(hb)));
    }
    uint2 H, L;
    H.x = ((uint32_t)h[1] << 16) | h[0]; H.y = ((uint32_t)h[3] << 16) | h[2];
    L.x = ((uint32_t)l[1] << 16) | l[0]; L.y = ((uint32_t)l[3] << 16) | l[2];
    ((uint2*)g_sh)[i] = H; ((uint2*)g_sl)[i] = L;
}
__global__ void norm_kernel(const float* __restrict__ seq) {
    int r = blockIdx.x * 128 + threadIdx.x;
    const float4* p = (const float4*)(seq + (size_t)r * 128);
    float s = 0.f;
#pragma unroll 8
    for (int i = 0; i < 32; i++) { float4 v = p[i]; s += v.x*v.x + v.y*v.y + v.z*v.z + v.w*v.w; }
    g_xn[r] = s;
}
__global__ void tsplit_kernel(const float* __restrict__ src, __half* __restrict__ dh,
                              __half* __restrict__ dl, int N) {
    __shared__ float t[32][33];
    int n0 = blockIdx.x * 32, k0 = blockIdx.y * 32;
    int tx = threadIdx.x, ty = threadIdx.y;
#pragma unroll
    for (int j = 0; j < 4; j++) t[ty + 8 * j][tx] = src[(size_t)(k0 + ty + 8 * j) * N + n0 + tx];
    __syncthreads();
#pragma unroll
    for (int j = 0; j < 4; j++) {
        int n = n0 + ty + 8 * j, k = k0 + tx;
        float v = t[tx][ty + 8 * j];
        __half hb = __float2half_rn(v);
        dh[(size_t)n * 128 + k] = hb;
        dl[(size_t)n * 128 + k] = __float2half_rn(v - __half2float(hb));
    }
}

// ---------------- KNN: fp16 hi-only pass + fp32 exact refine on 64-candidate pool ----------------
// pass1: A@0 (32K), B0@32768 (32K), B1@65536 (32K), stg@98304 (64K), xn@163840 (2x512B)
// tail:  qrow@0 (64K, fp32 queries), pool@98304 (32K), sc@131072 (32K)
#define KNSM 164864
__device__ __forceinline__ int stgoff(int q, int c) {   // XOR-swizzled f32 staging [128][128]
    return q * 128 + ((((c >> 2) ^ (q & 7)) << 2) | (c & 3));
}
__global__ __launch_bounds__(512, 1) void knn_kernel(const float* __restrict__ seq) {
    extern __shared__ char sm[];
    const uint32_t sA = s2u(sm);
    const int tid = threadIdx.x, lane = tid & 31, wid = tid >> 5;
    const int wm = wid & 3, wn = wid >> 2;               // 32x32 warp tile
    const int qt = blockIdx.x, b = blockIdx.y, fr = blockIdx.z;

    const size_t yoff = ((size_t)4 * NPTS + b * MP + qt * 128) * 128;
    const size_t xbase = ((size_t)fr * NPTS + b * MP) * 128;
    const float* xng = g_xn + fr * NPTS + b * MP;
    float* stg = (float*)(sm + 98304);

    fill_tile_async<512>(sA, g_sh + yoff, tid);
    fill_tile_async<512>(sA + 32768, g_sh + xbase, tid);           // chunk 0 -> B0
    if (tid < 32) CP16(sA + 163840 + tid * 16, xng + tid * 4);
    CP_COMMIT();

    float rd[16]; int ri[16];
#pragma unroll
    for (int j = 0; j < 16; j++) { rd[j] = 3.0e38f; ri[j] = 0; }
    const int q = tid >> 2, qu = tid & 3;                // 4 threads per query
    CP_WAIT0(); __syncthreads();

    for (int cc = 0; cc < 32; cc++) {
        const int cur = cc & 1, nxt = cur ^ 1;
        const uint32_t sBc = sA + 32768 + cur * 32768;
        if (cc + 1 < 32) {
            const uint32_t sBn = sA + 32768 + nxt * 32768;
            fill_tile_async<512>(sBn, g_sh + xbase + (size_t)(cc + 1) * 16384, tid);
            if (tid < 32) CP16(sA + 163840 + nxt * 512 + tid * 16, xng + (cc + 1) * 128 + tid * 4);
        }
        CP_COMMIT();

        float acc[2][4][4];
#pragma unroll
        for (int mi = 0; mi < 2; mi++)
#pragma unroll
            for (int ni = 0; ni < 4; ni++)
#pragma unroll
                for (int j = 0; j < 4; j++) acc[mi][ni][j] = 0.f;
#pragma unroll 1
        for (int ks = 0; ks < 8; ks++) {
            const int kc = ks * 16;
            uint32_t ah[2][4], bh[4][2];
#pragma unroll
            for (int mi = 0; mi < 2; mi++) ldmA(ah[mi], sA, wm * 32 + mi * 16, kc, lane);
#pragma unroll
            for (int ni = 0; ni < 4; ni++) ldmB(bh[ni], sBc, wn * 32 + ni * 8, kc, lane);
#pragma unroll
            for (int mi = 0; mi < 2; mi++)
#pragma unroll
                for (int ni = 0; ni < 4; ni++) mma16816(acc[mi][ni], ah[mi], bh[ni]);
        }
#pragma unroll
        for (int mi = 0; mi < 2; mi++)
#pragma unroll
            for (int ni = 0; ni < 4; ni++) {
                int r = wm * 32 + mi * 16 + (lane >> 2);
                int c = wn * 32 + ni * 8 + (lane & 3) * 2;
                *(float2*)&stg[stgoff(r, c)] = make_float2(acc[mi][ni][0], acc[mi][ni][1]);
                *(float2*)&stg[stgoff(r + 8, c)] = make_float2(acc[mi][ni][2], acc[mi][ni][3]);
            }
        __syncthreads();
        {   // all 512 threads: quarter qu scans 32 candidates for query q
            const float* xv = (const float*)(sm + 163840 + cur * 512);
#pragma unroll 4
            for (int c0 = 0; c0 < 32; c0++) {
                int c = qu * 32 + ((c0 + q + qu * 8) & 31);
                float s = xv[c] - 2.f * stg[stgoff(q, c)];
                if (s < rd[15]) {
                    rd[15] = s; ri[15] = cc * 128 + c;
#pragma unroll
                    for (int j = 15; j > 0; j--) {
                        if (rd[j] < rd[j - 1]) {
                            float tf = rd[j]; rd[j] = rd[j - 1]; rd[j - 1] = tf;
                            int tx = ri[j]; ri[j] = ri[j - 1]; ri[j - 1] = tx;
                        }
                    }
                }
            }
        }
        CP_WAIT0(); __syncthreads();                      // next B ready; stg reads done
    }

    // ---- tail: exact fp32 refine on 64-candidate pool ----
    int* pool = (int*)(sm + 98304);                       // [128][64]
#pragma unroll
    for (int j = 0; j < 16; j++) pool[q * 64 + qu * 16 + j] = ri[j];
    float* qrow = (float*)sm;                             // [128][128] fp32 queries
    {
        const float4* src = (const float4*)(seq + yoff);
#pragma unroll
        for (int i = tid; i < 4096; i += 512) ((float4*)qrow)[i] = src[i];
    }
    __syncthreads();

    float* sc = (float*)(sm + 131072);                    // [128][64]
    const float* xnf = g_xn + fr * NPTS + b * MP;
    {
        const int qq0 = wid * 8;
        for (int qq = 0; qq < 8; qq++) {
            const int qy = qq0 + qq;
            float4 qv = ((const float4*)(qrow + qy * 128))[lane];
#pragma unroll 2
            for (int j = 0; j < 64; j++) {
                int cand = pool[qy * 64 + j];
                const float4* crow = (const float4*)(seq + xbase + (size_t)cand * 128);
                float4 cv = crow[lane];
                float p = qv.x * cv.x + qv.y * cv.y + qv.z * cv.z + qv.w * cv.w;
#pragma unroll
                for (int o = 16; o; o >>= 1) p += __shfl_xor_sync(0xffffffffu, p, o);
                if (lane == 0) sc[qy * 64 + j] = xnf[cand] - 2.f * p;
            }
        }
    }
    __syncthreads();
    if (tid < 128) {                                      // exact tie-stable top-16 of 64
        float bd[16]; int bi[16];
#pragma unroll
        for (int j = 0; j < 16; j++) { bd[j] = 3.0e38f; bi[j] = 0x7fffffff; }
        for (int j = 0; j < 64; j++) {
            float s = sc[tid * 64 + j]; int ci = pool[tid * 64 + j];
            if (s < bd[15] || (s == bd[15] && ci < bi[15])) {
                bd[15] = s; bi[15] = ci;
#pragma unroll
                for (int k = 15; k > 0; k--) {
                    if (bd[k] < bd[k - 1] || (bd[k] == bd[k - 1] && bi[k] < bi[k - 1])) {
                        float tf = bd[k]; bd[k] = bd[k - 1]; bd[k - 1] = tf;
                        int tx = bi[k]; bi[k] = bi[k - 1]; bi[k - 1] = tx;
                    }
                }
            }
        }
        const size_t nrow = ((size_t)fr * NPTS + b * MP + qt * 128 + tid) * KNB;
#pragma unroll
        for (int j = 0; j < 16; j++) g_nbr[nrow + j] = b * MP + bi[j];
    }
}

// ---------------- fused H1 + gf: A resident, W2 streamed double-buffered ----------------
#define GFSM 196608
__global__ __launch_bounds__(256, 1) void gf_kernel(const float* __restrict__ b1,
                                                    const float* __restrict__ b2) {
    extern __shared__ char sm[];
    const uint32_t sA = s2u(sm), sB0 = sA + 65536, sB1 = sA + 131072;
    const int tid = threadIdx.x, lane = tid & 31, wid = tid >> 5;
    const int wm = wid & 1, wn = wid >> 1;
    const size_t row0 = (size_t)blockIdx.x * 128;

    fill_tile_async<256>(sA, g_sh + row0 * 128, tid);
    fill_tile_async<256>(sA + 32768, g_sl + row0 * 128, tid);
    fill_tile_async<256>(sB0, g_w1h, tid);
    fill_tile_async<256>(sB0 + 32768, g_w1l, tid);
    CP_COMMIT(); CP_WAIT0(); __syncthreads();

    float acc[4][4][4];
    ACC_ZERO4(acc);
    mma_core(sA, sB0, wm, wn, lane, acc);
    __syncthreads();

    fill_tile_async<256>(sB0, g_w2h, tid); fill_tile_async<256>(sB0 + 32768, g_w2l, tid); CP_COMMIT();
    fill_tile_async<256>(sB1, g_w2h + 16384, tid); fill_tile_async<256>(sB1 + 32768, g_w2l + 16384, tid); CP_COMMIT();

#pragma unroll
    for (int mi = 0; mi < 4; mi++)
#pragma unroll
        for (int ni = 0; ni < 4; ni++) {
            int r = wm * 64 + mi * 16 + (lane >> 2);
            int c = wn * 32 + ni * 8 + (lane & 3) * 2;
            float2 bv = *(const float2*)(b1 + c);
#pragma unroll
            for (int half = 0; half < 2; half++) {
                int rr = r + half * 8;
                float v0 = leaky_f(acc[mi][ni][half * 2]     + bv.x);
                float v1 = leaky_f(acc[mi][ni][half * 2 + 1] + bv.y);
                __half h0 = __float2half_rn(v0), h1 = __float2half_rn(v1);
                __half l0 = __float2half_rn(v0 - __half2float(h0));
                __half l1 = __float2half_rn(v1 - __half2float(h1));
                uint32_t off = tile_off(rr, c >> 3) + (c & 7) * 2;
                *(uint32_t*)(sm + off) =
                    ((uint32_t)__half_as_ushort(h1) << 16) | __half_as_ushort(h0);
                *(uint32_t*)(sm + 32768 + off) =
                    ((uint32_t)__half_as_ushort(l1) << 16) | __half_as_ushort(l0);
            }
        }
    __syncthreads();

    const int t = (int)(row0 >> 14), b = (int)((row0 >> 12) & 3);
    float* gfrow = g_gf + (t * 4 + b) * 1024;
    const float inv = 1.f / 4096.f;

    for (int nb = 0; nb < 8; nb++) {
        CP_WAIT1(); __syncthreads();
        ACC_ZERO4(acc);
        mma_core(sA, (nb & 1) ? sB1 : sB0, wm, wn, lane, acc);
        __syncthreads();
        if (nb + 2 < 8) {
            uint32_t dst = (nb & 1) ? sB1 : sB0;
            fill_tile_async<256>(dst, g_w2h + (nb + 2) * 16384, tid);
            fill_tile_async<256>(dst + 32768, g_w2l + (nb + 2) * 16384, tid);
        }
        CP_COMMIT();
#pragma unroll
        for (int ni = 0; ni < 4; ni++) {
            int c = wn * 32 + ni * 8 + (lane & 3) * 2;
            float2 bv = *(const float2*)(b2 + nb * 128 + c);
            float s0 = 0.f, s1 = 0.f;
#pragma unroll
            for (int mi = 0; mi < 4; mi++) {
                s0 += leaky_f(acc[mi][ni][0] + bv.x) + leaky_f(acc[mi][ni][2] + bv.x);
                s1 += leaky_f(acc[mi][ni][1] + bv.y) + leaky_f(acc[mi][ni][3] + bv.y);
            }
#pragma unroll
            for (int o = 4; o <= 16; o <<= 1) {
                s0 += __shfl_xor_sync(0xffffffffu, s0, o);
                s1 += __shfl_xor_sync(0xffffffffu, s1, o);
            }
            if (lane < 4) {
                atomicAdd(&gfrow[nb * 128 + c], s0 * inv);
                atomicAdd(&gfrow[nb * 128 + c + 1], s1 * inv);
            }
        }
    }
}

// ---------------- XLR ----------------
#define XLSM 196608
__global__ __launch_bounds__(256, 1) void xlr_kernel() {
    extern __shared__ char sm[];
    const uint32_t sA = s2u(sm), sB0 = sA + 65536, sB1 = sA + 131072;
    const int tid = threadIdx.x, lane = tid & 31, wid = tid >> 5;
    const int wm = wid & 1, wn = wid >> 1;
    const int z = blockIdx.y;
    const size_t row0 = (size_t)blockIdx.x * 128;
    const __half* Wh = (z == 4) ? g_wlh : g_wrh;
    const __half* Wl = (z == 4) ? g_wll : g_wrl;

    fill_tile_async<256>(sA, g_sh + ((size_t)z * NPTS + row0) * 128, tid);
    fill_tile_async<256>(sA + 32768, g_sl + ((size_t)z * NPTS + row0) * 128, tid);
    fill_tile_async<256>(sB0, Wh, tid); fill_tile_async<256>(sB0 + 32768, Wl, tid); CP_COMMIT();
    fill_tile_async<256>(sB1, Wh + 16384, tid); fill_tile_async<256>(sB1 + 32768, Wl + 16384, tid); CP_COMMIT();

    float* dstb = g_XLR + ((size_t)z * NPTS + row0) * 512;
    for (int nb = 0; nb < 4; nb++) {
        CP_WAIT1(); __syncthreads();
        float acc[4][4][4];
        ACC_ZERO4(acc);
        mma_core(sA, (nb & 1) ? sB1 : sB0, wm, wn, lane, acc);
        __syncthreads();
        if (nb + 2 < 4) {
            uint32_t dst = (nb & 1) ? sB1 : sB0;
            fill_tile_async<256>(dst, Wh + (nb + 2) * 16384, tid);
            fill_tile_async<256>(dst + 32768, Wl + (nb + 2) * 16384, tid);
        }
        CP_COMMIT();
#pragma unroll
        for (int mi = 0; mi < 4; mi++)
#pragma unroll
            for (int ni = 0; ni < 4; ni++) {
                int r = wm * 64 + mi * 16 + (lane >> 2);
                int c = wn * 32 + ni * 8 + (lane & 3) * 2;
                *(float2*)(dstb + (size_t)r * 512 + nb * 128 + c) =
                    make_float2(acc[mi][ni][0], acc[mi][ni][1]);
                *(float2*)(dstb + (size_t)(r + 8) * 512 + nb * 128 + c) =
                    make_float2(acc[mi][ni][2], acc[mi][ni][3]);
            }
    }
}

// ---------------- attn / gat / final ----------------
__global__ void attn_kernel() {
    __shared__ float sc[16];
    const int tid = threadIdx.x, w = tid >> 5, lane = tid & 31;
    const int b = w >> 2, t = w & 3;
    float acc = 0.f;
    for (int g = lane; g < 1024; g += 32)
        acc += g_gf[(16 + b) * 1024 + g] * g_gf[(t * 4 + b) * 1024 + g];
#pragma unroll
    for (int o = 16; o; o >>= 1) acc += __shfl_xor_sync(0xffffffffu, acc, o);
    if (lane == 0) sc[b * 4 + t] = acc * (1.f / 32.f);
    __syncthreads();
    if (tid < 4) {
        int bb = tid;
        float m = sc[bb * 4];
        for (int i = 1; i < 4; i++) m = fmaxf(m, sc[bb * 4 + i]);
        float e[4], s = 0.f;
        for (int i = 0; i < 4; i++) { e[i] = expf(sc[bb * 4 + i] - m); s += e[i]; }
        for (int i = 0; i < 4; i++) g_attn[bb * 4 + i] = e[i] / s;
    }
}
__global__ __launch_bounds__(128) void gat_kernel(const float* __restrict__ att_w) {
    __shared__ float xls[16 * 512], xrs[512], aws[512], es[64], as_[64];
    __shared__ int nb[16];
    const int tid = threadIdx.x, n = blockIdx.x, fr = blockIdx.y;
    const float* XL = g_XLR + (size_t)4 * NPTS * 512;
    const float* XR = g_XLR + (size_t)fr * NPTS * 512;
    *(float4*)&xrs[tid * 4] = *(const float4*)(XR + (size_t)n * 512 + tid * 4);
    *(float4*)&aws[tid * 4] = *(const float4*)(att_w + tid * 4);
    if (tid < 16) nb[tid] = g_nbr[((size_t)fr * NPTS + n) * KNB + tid];
    __syncthreads();
#pragma unroll
    for (int k = 0; k < 16; k++)
        *(float4*)&xls[k * 512 + tid * 4] = *(const float4*)(XL + (size_t)nb[k] * 512 + tid * 4);
    __syncthreads();
    {
        const int pr = tid >> 1, hf = tid & 1;
        const int k = pr & 15, h = pr >> 4;
        float acc = 0.f;
#pragma unroll 4
        for (int c0 = 0; c0 < 64; c0++) {
            int c = hf * 64 + ((c0 + pr + hf * 16) & 63);
            float v = xls[k * 512 + h * 128 + c] + xrs[h * 128 + c];
            acc += aws[h * 128 + c] * (v < 0.f ? 0.2f * v : v);
        }
        acc += __shfl_xor_sync(0xffffffffu, acc, 1);
        if (!hf) es[h * 16 + k] = acc;
    }
    __syncthreads();
    if (tid < 4) {
        const int h = tid;
        float m = -1e30f;
        for (int k = 0; k < 16; k++) m = fmaxf(m, es[h * 16 + k]);
        float ex[16], s = 0.f;
        for (int k = 0; k < 16; k++) { ex[k] = expf(es[h * 16 + k] - m); s += ex[k]; }
        for (int k = 0; k < 16; k++) as_[h * 16 + k] = ex[k] / s;
    }
    __syncthreads();
    float o = 0.f;
#pragma unroll
    for (int h = 0; h < 4; h++) {
        float oh = 0.f;
#pragma unroll
        for (int k = 0; k < 16; k++) oh += as_[h * 16 + k] * xls[k * 512 + h * 128 + tid];
        o += oh;
    }
    g_res[((size_t)fr * NPTS + n) * 128 + tid] = o * 0.25f;
}
__global__ __launch_bounds__(128) void final_kernel(const float* __restrict__ seq, float* __restrict__ out) {
    const int n = blockIdx.x, c = threadIdx.x, b = n >> 12;
    float w = 0.f;
#pragma unroll
    for (int i = 0; i < 4; i++)
        w += g_attn[b * 4 + i] * g_res[((size_t)i * NPTS + n) * 128 + c];
    const float* last = seq + (size_t)4 * NPTS * 128;
    out[(size_t)n * 256 + c] = last[(size_t)n * 128 + c];
    out[(size_t)n * 256 + 128 + c] = w;
}

// ---------------- launch (knn at my #4: harness adds ~2 launches, ncu -s 5 captures #6) ----------------
extern "C" void kernel_launch(void* const* d_in, const int* in_sizes, int n_in,
                              void* d_out, int out_size) {
    (void)in_sizes; (void)n_in; (void)out_size;
    const float* seq = (const float*)d_in[0];
    const float* W1  = (const float*)d_in[1];
    const float* b1  = (const float*)d_in[2];
    const float* W2  = (const float*)d_in[3];
    const float* b2  = (const float*)d_in[4];
    const float* Wl  = (const float*)d_in[5];
    const float* Wr  = (const float*)d_in[6];
    const float* aw  = (const float*)d_in[7];
    float* out = (float*)d_out;

    __half *pw1h, *pw1l, *pw2h, *pw2l, *pwlh, *pwll, *pwrh, *pwrl;
    cudaGetSymbolAddress((void**)&pw1h, g_w1h); cudaGetSymbolAddress((void**)&pw1l, g_w1l);
    cudaGetSymbolAddress((void**)&pw2h, g_w2h); cudaGetSymbolAddress((void**)&pw2l, g_w2l);
    cudaGetSymbolAddress((void**)&pwlh, g_wlh); cudaGetSymbolAddress((void**)&pwll, g_wll);
    cudaGetSymbolAddress((void**)&pwrh, g_wrh); cudaGetSymbolAddress((void**)&pwrl, g_wrl);

    cudaFuncSetAttribute(gf_kernel,  cudaFuncAttributeMaxDynamicSharedMemorySize, GFSM);
    cudaFuncSetAttribute(xlr_kernel, cudaFuncAttributeMaxDynamicSharedMemorySize, XLSM);
    cudaFuncSetAttribute(knn_kernel, cudaFuncAttributeMaxDynamicSharedMemorySize, KNSM);

    zero_gf_kernel<<<80, 256>>>();                               // 1
    split_seq_kernel<<<10240, 256>>>(seq);                       // 2
    norm_kernel<<<512, 128>>>(seq);                              // 3
    knn_kernel<<<dim3(32, 4, 4), 512, KNSM>>>(seq);              // 4 <- ncu target
    tsplit_kernel<<<dim3(4, 4),  dim3(32, 8)>>>(W1, pw1h, pw1l, 128);
    tsplit_kernel<<<dim3(32, 4), dim3(32, 8)>>>(W2, pw2h, pw2l, 1024);
    tsplit_kernel<<<dim3(16, 4), dim3(32, 8)>>>(Wl, pwlh, pwll, 512);
    tsplit_kernel<<<dim3(16, 4), dim3(32, 8)>>>(Wr, pwrh, pwrl, 512);
    gf_kernel<<<640, 256, GFSM>>>(b1, b2);
    attn_kernel<<<1, 512>>>();
    xlr_kernel<<<dim3(128, 5), 256, XLSM>>>();
    gat_kernel<<<dim3(NPTS, 4), 128>>>(aw);
    final_kernel<<<NPTS, 128>>>(seq, out);
}

// round 10
// speedup vs baseline: 1.0257x; 1.0257x over previous
#include <cuda_runtime.h>
#include <cuda_fp16.h>
#include <cstdint>

#define NPTS 16384
#define MP   4096
#define KNB  16

// ---------------- helpers ----------------
__device__ __forceinline__ uint32_t s2u(const void* p) {
    uint32_t a;
    asm("{ .reg .u64 t; cvta.to.shared.u64 t, %1; cvt.u32.u64 %0, t; }" : "=r"(a) : "l"(p));
    return a;
}
#define CP16(dst, src) asm volatile("cp.async.cg.shared.global [%0], [%1], 16;" :: "r"(dst), "l"(src))
#define CP_COMMIT()    asm volatile("cp.async.commit_group;" ::: "memory")
#define CP_WAIT0()     asm volatile("cp.async.wait_group 0;" ::: "memory")
#define CP_WAIT1()     asm volatile("cp.async.wait_group 1;" ::: "memory")

// [128][128] f16 tile, 256B rows, 16B chunks XOR-swizzled by row
__device__ __forceinline__ uint32_t tile_off(int r, int c16) {
    return (uint32_t)(r * 256 + ((c16 ^ (r & 7)) << 4));
}
template <int NT>
__device__ __forceinline__ void fill_tile_async(uint32_t dst, const __half* __restrict__ src, int tid) {
#pragma unroll
    for (int it = 0; it < 2048 / NT; it++) {
        int idx = tid + it * NT;
        int r = idx >> 4, c16 = idx & 15;
        CP16(dst + tile_off(r, c16), src + r * 128 + c16 * 8);
    }
}
__device__ __forceinline__ void ldmA(uint32_t* a, uint32_t base, int mrow, int kcol, int lane) {
    uint32_t addr = base + tile_off(mrow + (lane & 15), (kcol >> 3) + (lane >> 4));
    asm volatile("ldmatrix.sync.aligned.m8n8.x4.shared.b16 {%0,%1,%2,%3}, [%4];"
        : "=r"(a[0]), "=r"(a[1]), "=r"(a[2]), "=r"(a[3]) : "r"(addr));
}
__device__ __forceinline__ void ldmB(uint32_t* b, uint32_t base, int ncol, int kcol, int lane) {
    uint32_t addr = base + tile_off(ncol + (lane & 7), (kcol >> 3) + ((lane >> 3) & 1));
    asm volatile("ldmatrix.sync.aligned.m8n8.x2.shared.b16 {%0,%1}, [%2];"
        : "=r"(b[0]), "=r"(b[1]) : "r"(addr));
}
__device__ __forceinline__ void mma16816(float* d, const uint32_t* a, const uint32_t* b) {
    asm volatile("mma.sync.aligned.m16n8k16.row.col.f32.f16.f16.f32 "
        "{%0,%1,%2,%3}, {%4,%5,%6,%7}, {%8,%9}, {%0,%1,%2,%3};"
        : "+f"(d[0]), "+f"(d[1]), "+f"(d[2]), "+f"(d[3])
        : "r"(a[0]), "r"(a[1]), "r"(a[2]), "r"(a[3]), "r"(b[0]), "r"(b[1]));
}
__device__ __forceinline__ float leaky_f(float v) { return v < 0.f ? 0.2f * v : v; }

// split-f16 3-product 128x128x128 tile for 8 warps: warp (wm,wn) owns 64x32
__device__ __forceinline__ void mma_core(uint32_t sA, uint32_t sB, int wm, int wn, int lane,
                                         float acc[4][4][4]) {
#pragma unroll 1
    for (int ks = 0; ks < 8; ks++) {
        const int kc = ks * 16;
        uint32_t ah[4][4], al[4][4], bh[4][2], bl[4][2];
#pragma unroll
        for (int mi = 0; mi < 4; mi++) {
            ldmA(ah[mi], sA, wm * 64 + mi * 16, kc, lane);
            ldmA(al[mi], sA + 32768, wm * 64 + mi * 16, kc, lane);
        }
#pragma unroll
        for (int ni = 0; ni < 4; ni++) {
            ldmB(bh[ni], sB, wn * 32 + ni * 8, kc, lane);
            ldmB(bl[ni], sB + 32768, wn * 32 + ni * 8, kc, lane);
        }
#pragma unroll
        for (int mi = 0; mi < 4; mi++)
#pragma unroll
            for (int ni = 0; ni < 4; ni++) {
                mma16816(acc[mi][ni], ah[mi], bh[ni]);
                mma16816(acc[mi][ni], ah[mi], bl[ni]);
                mma16816(acc[mi][ni], al[mi], bh[ni]);
            }
    }
}
#define ACC_ZERO4(acc) do { \
    _Pragma("unroll") for (int mi = 0; mi < 4; mi++) \
    _Pragma("unroll") for (int ni = 0; ni < 4; ni++) \
    _Pragma("unroll") for (int j = 0; j < 4; j++) acc[mi][ni][j] = 0.f; } while (0)

// ---------------- scratch ----------------
__device__ __half g_sh[81920 * 128], g_sl[81920 * 128];
__device__ __half g_w1h[128 * 128],  g_w1l[128 * 128];
__device__ __half g_w2h[1024 * 128], g_w2l[1024 * 128];
__device__ __half g_wlh[512 * 128],  g_wll[512 * 128];
__device__ __half g_wrh[512 * 128],  g_wrl[512 * 128];
__device__ float g_xn[65536];
__device__ __half g_XLR[5 * 16384 * 512];     // fp16 now (84 MB)
__device__ float g_gf[5 * 4 * 1024];
__device__ float g_attn[16];
__device__ int   g_nbr[4 * 16384 * 16];
__device__ float g_res[4 * 16384 * 128];

// ---------------- preludes ----------------
__global__ void zero_gf_kernel() {
    int i = blockIdx.x * 256 + threadIdx.x;
    if (i < 5 * 4 * 1024) g_gf[i] = 0.f;
}
__global__ void split_seq_kernel(const float* __restrict__ seq) {
    size_t i = (size_t)blockIdx.x * 256 + threadIdx.x;
    float4 v = ((const float4*)seq)[i];
    float x[4] = {v.x, v.y, v.z, v.w};
    unsigned short h[4], l[4];
#pragma unroll
    for (int j = 0; j < 4; j++) {
        __half hb = __float2half_rn(x[j]);
        h[j] = __half_as_ushort(hb);
        l[j] = __half_as_ushort(__float2half_rn(x[j] - __half2float(hb)));
    }
    uint2 H, L;
    H.x = ((uint32_t)h[1] << 16) | h[0]; H.y = ((uint32_t)h[3] << 16) | h[2];
    L.x = ((uint32_t)l[1] << 16) | l[0]; L.y = ((uint32_t)l[3] << 16) | l[2];
    ((uint2*)g_sh)[i] = H; ((uint2*)g_sl)[i] = L;
}
__global__ void norm_kernel(const float* __restrict__ seq) {
    int r = blockIdx.x * 128 + threadIdx.x;
    const float4* p = (const float4*)(seq + (size_t)r * 128);
    float s = 0.f;
#pragma unroll 8
    for (int i = 0; i < 32; i++) { float4 v = p[i]; s += v.x*v.x + v.y*v.y + v.z*v.z + v.w*v.w; }
    g_xn[r] = s;
}
__global__ void tsplit_kernel(const float* __restrict__ src, __half* __restrict__ dh,
                              __half* __restrict__ dl, int N) {
    __shared__ float t[32][33];
    int n0 = blockIdx.x * 32, k0 = blockIdx.y * 32;
    int tx = threadIdx.x, ty = threadIdx.y;
#pragma unroll
    for (int j = 0; j < 4; j++) t[ty + 8 * j][tx] = src[(size_t)(k0 + ty + 8 * j) * N + n0 + tx];
    __syncthreads();
#pragma unroll
    for (int j = 0; j < 4; j++) {
        int n = n0 + ty + 8 * j, k = k0 + tx;
        float v = t[tx][ty + 8 * j];
        __half hb = __float2half_rn(v);
        dh[(size_t)n * 128 + k] = hb;
        dl[(size_t)n * 128 + k] = __float2half_rn(v - __half2float(hb));
    }
}

// ---------------- KNN: fp16 hi-only pass + fp32 exact refine on 64-candidate pool ----------------
// pass1: A@0 (32K), B0@32768 (32K), B1@65536 (32K), stg@98304 (64K), xn@163840 (2x512B)
// tail:  qrow@0 (64K, fp32 queries), pool@98304 (32K), sc@131072 (32K)
#define KNSM 164864
__device__ __forceinline__ int stgoff(int q, int c) {   // XOR-swizzled f32 staging [128][128]
    return q * 128 + ((((c >> 2) ^ (q & 7)) << 2) | (c & 3));
}
__global__ __launch_bounds__(512, 1) void knn_kernel(const float* __restrict__ seq) {
    extern __shared__ char sm[];
    const uint32_t sA = s2u(sm);
    const int tid = threadIdx.x, lane = tid & 31, wid = tid >> 5;
    const int wm = wid & 3, wn = wid >> 2;               // 32x32 warp tile
    const int qt = blockIdx.x, b = blockIdx.y, fr = blockIdx.z;

    const size_t yoff = ((size_t)4 * NPTS + b * MP + qt * 128) * 128;
    const size_t xbase = ((size_t)fr * NPTS + b * MP) * 128;
    const float* xng = g_xn + fr * NPTS + b * MP;
    float* stg = (float*)(sm + 98304);

    fill_tile_async<512>(sA, g_sh + yoff, tid);
    fill_tile_async<512>(sA + 32768, g_sh + xbase, tid);           // chunk 0 -> B0
    if (tid < 32) CP16(sA + 163840 + tid * 16, xng + tid * 4);
    CP_COMMIT();

    float rd[16]; int ri[16];
#pragma unroll
    for (int j = 0; j < 16; j++) { rd[j] = 3.0e38f; ri[j] = 0; }
    const int q = tid >> 2, qu = tid & 3;                // 4 threads per query
    CP_WAIT0(); __syncthreads();

    for (int cc = 0; cc < 32; cc++) {
        const int cur = cc & 1, nxt = cur ^ 1;
        const uint32_t sBc = sA + 32768 + cur * 32768;
        if (cc + 1 < 32) {
            const uint32_t sBn = sA + 32768 + nxt * 32768;
            fill_tile_async<512>(sBn, g_sh + xbase + (size_t)(cc + 1) * 16384, tid);
            if (tid < 32) CP16(sA + 163840 + nxt * 512 + tid * 16, xng + (cc + 1) * 128 + tid * 4);
        }
        CP_COMMIT();

        float acc[2][4][4];
#pragma unroll
        for (int mi = 0; mi < 2; mi++)
#pragma unroll
            for (int ni = 0; ni < 4; ni++)
#pragma unroll
                for (int j = 0; j < 4; j++) acc[mi][ni][j] = 0.f;
#pragma unroll 1
        for (int ks = 0; ks < 8; ks++) {
            const int kc = ks * 16;
            uint32_t ah[2][4], bh[4][2];
#pragma unroll
            for (int mi = 0; mi < 2; mi++) ldmA(ah[mi], sA, wm * 32 + mi * 16, kc, lane);
#pragma unroll
            for (int ni = 0; ni < 4; ni++) ldmB(bh[ni], sBc, wn * 32 + ni * 8, kc, lane);
#pragma unroll
            for (int mi = 0; mi < 2; mi++)
#pragma unroll
                for (int ni = 0; ni < 4; ni++) mma16816(acc[mi][ni], ah[mi], bh[ni]);
        }
#pragma unroll
        for (int mi = 0; mi < 2; mi++)
#pragma unroll
            for (int ni = 0; ni < 4; ni++) {
                int r = wm * 32 + mi * 16 + (lane >> 2);
                int c = wn * 32 + ni * 8 + (lane & 3) * 2;
                *(float2*)&stg[stgoff(r, c)] = make_float2(acc[mi][ni][0], acc[mi][ni][1]);
                *(float2*)&stg[stgoff(r + 8, c)] = make_float2(acc[mi][ni][2], acc[mi][ni][3]);
            }
        __syncthreads();
        {   // vectorized scan: quarter qu, 8 float4 groups (1 LDS.128 per 4 candidates)
            const float4* xv4 = (const float4*)(sm + 163840 + cur * 512);
            const float4* st4 = (const float4*)stg;
            const int qb = q * 32, qx = q & 7;
#pragma unroll
            for (int g0 = 0; g0 < 8; g0++) {
                const int g = qu * 8 + g0;               // candidate group (c = g*4 + j)
                float4 sv = st4[qb + (g ^ qx)];          // swizzled, conflict-free
                float4 xq = xv4[g];                      // broadcast across q
                float s0 = fmaf(-2.f, sv.x, xq.x), s1 = fmaf(-2.f, sv.y, xq.y);
                float s2 = fmaf(-2.f, sv.z, xq.z), s3 = fmaf(-2.f, sv.w, xq.w);
                float svals[4] = {s0, s1, s2, s3};
#pragma unroll
                for (int j = 0; j < 4; j++) {
                    if (svals[j] < rd[15]) {
                        rd[15] = svals[j]; ri[15] = cc * 128 + g * 4 + j;
#pragma unroll
                        for (int k = 15; k > 0; k--) {
                            if (rd[k] < rd[k - 1]) {
                                float tf = rd[k]; rd[k] = rd[k - 1]; rd[k - 1] = tf;
                                int tx = ri[k]; ri[k] = ri[k - 1]; ri[k - 1] = tx;
                            }
                        }
                    }
                }
            }
        }
        CP_WAIT0(); __syncthreads();                      // next B ready; stg reads done
    }

    // ---- tail: exact fp32 refine on 64-candidate pool ----
    int* pool = (int*)(sm + 98304);                       // [128][64]
#pragma unroll
    for (int j = 0; j < 16; j++) pool[q * 64 + qu * 16 + j] = ri[j];
    float* qrow = (float*)sm;                             // [128][128] fp32 queries
    {
        const float4* src = (const float4*)(seq + yoff);
#pragma unroll
        for (int i = tid; i < 4096; i += 512) ((float4*)qrow)[i] = src[i];
    }
    __syncthreads();

    float* sc = (float*)(sm + 131072);                    // [128][64]
    const float* xnf = g_xn + fr * NPTS + b * MP;
    {
        const int qq0 = wid * 8;
        for (int qq = 0; qq < 8; qq++) {
            const int qy = qq0 + qq;
            float4 qv = ((const float4*)(qrow + qy * 128))[lane];
#pragma unroll 2
            for (int j = 0; j < 64; j++) {
                int cand = pool[qy * 64 + j];
                const float4* crow = (const float4*)(seq + xbase + (size_t)cand * 128);
                float4 cv = crow[lane];
                float p = qv.x * cv.x + qv.y * cv.y + qv.z * cv.z + qv.w * cv.w;
#pragma unroll
                for (int o = 16; o; o >>= 1) p += __shfl_xor_sync(0xffffffffu, p, o);
                if (lane == 0) sc[qy * 64 + j] = xnf[cand] - 2.f * p;
            }
        }
    }
    __syncthreads();
    if (tid < 128) {                                      // exact tie-stable top-16 of 64
        float bd[16]; int bi[16];
#pragma unroll
        for (int j = 0; j < 16; j++) { bd[j] = 3.0e38f; bi[j] = 0x7fffffff; }
        for (int j = 0; j < 64; j++) {
            float s = sc[tid * 64 + j]; int ci = pool[tid * 64 + j];
            if (s < bd[15] || (s == bd[15] && ci < bi[15])) {
                bd[15] = s; bi[15] = ci;
#pragma unroll
                for (int k = 15; k > 0; k--) {
                    if (bd[k] < bd[k - 1] || (bd[k] == bd[k - 1] && bi[k] < bi[k - 1])) {
                        float tf = bd[k]; bd[k] = bd[k - 1]; bd[k - 1] = tf;
                        int tx = bi[k]; bi[k] = bi[k - 1]; bi[k - 1] = tx;
                    }
                }
            }
        }
        const size_t nrow = ((size_t)fr * NPTS + b * MP + qt * 128 + tid) * KNB;
#pragma unroll
        for (int j = 0; j < 16; j++) g_nbr[nrow + j] = b * MP + bi[j];
    }
}

// ---------------- fused H1 + gf: A resident, W2 streamed double-buffered ----------------
#define GFSM 196608
__global__ __launch_bounds__(256, 1) void gf_kernel(const float* __restrict__ b1,
                                                    const float* __restrict__ b2) {
    extern __shared__ char sm[];
    const uint32_t sA = s2u(sm), sB0 = sA + 65536, sB1 = sA + 131072;
    const int tid = threadIdx.x, lane = tid & 31, wid = tid >> 5;
    const int wm = wid & 1, wn = wid >> 1;
    const size_t row0 = (size_t)blockIdx.x * 128;

    fill_tile_async<256>(sA, g_sh + row0 * 128, tid);
    fill_tile_async<256>(sA + 32768, g_sl + row0 * 128, tid);
    fill_tile_async<256>(sB0, g_w1h, tid);
    fill_tile_async<256>(sB0 + 32768, g_w1l, tid);
    CP_COMMIT(); CP_WAIT0(); __syncthreads();

    float acc[4][4][4];
    ACC_ZERO4(acc);
    mma_core(sA, sB0, wm, wn, lane, acc);
    __syncthreads();

    fill_tile_async<256>(sB0, g_w2h, tid); fill_tile_async<256>(sB0 + 32768, g_w2l, tid); CP_COMMIT();
    fill_tile_async<256>(sB1, g_w2h + 16384, tid); fill_tile_async<256>(sB1 + 32768, g_w2l + 16384, tid); CP_COMMIT();

#pragma unroll
    for (int mi = 0; mi < 4; mi++)
#pragma unroll
        for (int ni = 0; ni < 4; ni++) {
            int r = wm * 64 + mi * 16 + (lane >> 2);
            int c = wn * 32 + ni * 8 + (lane & 3) * 2;
            float2 bv = *(const float2*)(b1 + c);
#pragma unroll
            for (int half = 0; half < 2; half++) {
                int rr = r + half * 8;
                float v0 = leaky_f(acc[mi][ni][half * 2]     + bv.x);
                float v1 = leaky_f(acc[mi][ni][half * 2 + 1] + bv.y);
                __half h0 = __float2half_rn(v0), h1 = __float2half_rn(v1);
                __half l0 = __float2half_rn(v0 - __half2float(h0));
                __half l1 = __float2half_rn(v1 - __half2float(h1));
                uint32_t off = tile_off(rr, c >> 3) + (c & 7) * 2;
                *(uint32_t*)(sm + off) =
                    ((uint32_t)__half_as_ushort(h1) << 16) | __half_as_ushort(h0);
                *(uint32_t*)(sm + 32768 + off) =
                    ((uint32_t)__half_as_ushort(l1) << 16) | __half_as_ushort(l0);
            }
        }
    __syncthreads();

    const int t = (int)(row0 >> 14), b = (int)((row0 >> 12) & 3);
    float* gfrow = g_gf + (t * 4 + b) * 1024;
    const float inv = 1.f / 4096.f;

    for (int nb = 0; nb < 8; nb++) {
        CP_WAIT1(); __syncthreads();
        ACC_ZERO4(acc);
        mma_core(sA, (nb & 1) ? sB1 : sB0, wm, wn, lane, acc);
        __syncthreads();
        if (nb + 2 < 8) {
            uint32_t dst = (nb & 1) ? sB1 : sB0;
            fill_tile_async<256>(dst, g_w2h + (nb + 2) * 16384, tid);
            fill_tile_async<256>(dst + 32768, g_w2l + (nb + 2) * 16384, tid);
        }
        CP_COMMIT();
#pragma unroll
        for (int ni = 0; ni < 4; ni++) {
            int c = wn * 32 + ni * 8 + (lane & 3) * 2;
            float2 bv = *(const float2*)(b2 + nb * 128 + c);
            float s0 = 0.f, s1 = 0.f;
#pragma unroll
            for (int mi = 0; mi < 4; mi++) {
                s0 += leaky_f(acc[mi][ni][0] + bv.x) + leaky_f(acc[mi][ni][2] + bv.x);
                s1 += leaky_f(acc[mi][ni][1] + bv.y) + leaky_f(acc[mi][ni][3] + bv.y);
            }
#pragma unroll
            for (int o = 4; o <= 16; o <<= 1) {
                s0 += __shfl_xor_sync(0xffffffffu, s0, o);
                s1 += __shfl_xor_sync(0xffffffffu, s1, o);
            }
            if (lane < 4) {
                atomicAdd(&gfrow[nb * 128 + c], s0 * inv);
                atomicAdd(&gfrow[nb * 128 + c + 1], s1 * inv);
            }
        }
    }
}

// ---------------- XLR: fp16 output ----------------
#define XLSM 196608
__global__ __launch_bounds__(256, 1) void xlr_kernel() {
    extern __shared__ char sm[];
    const uint32_t sA = s2u(sm), sB0 = sA + 65536, sB1 = sA + 131072;
    const int tid = threadIdx.x, lane = tid & 31, wid = tid >> 5;
    const int wm = wid & 1, wn = wid >> 1;
    const int z = blockIdx.y;
    const size_t row0 = (size_t)blockIdx.x * 128;
    const __half* Wh = (z == 4) ? g_wlh : g_wrh;
    const __half* Wl = (z == 4) ? g_wll : g_wrl;

    fill_tile_async<256>(sA, g_sh + ((size_t)z * NPTS + row0) * 128, tid);
    fill_tile_async<256>(sA + 32768, g_sl + ((size_t)z * NPTS + row0) * 128, tid);
    fill_tile_async<256>(sB0, Wh, tid); fill_tile_async<256>(sB0 + 32768, Wl, tid); CP_COMMIT();
    fill_tile_async<256>(sB1, Wh + 16384, tid); fill_tile_async<256>(sB1 + 32768, Wl + 16384, tid); CP_COMMIT();

    __half* dstb = g_XLR + ((size_t)z * NPTS + row0) * 512;
    for (int nb = 0; nb < 4; nb++) {
        CP_WAIT1(); __syncthreads();
        float acc[4][4][4];
        ACC_ZERO4(acc);
        mma_core(sA, (nb & 1) ? sB1 : sB0, wm, wn, lane, acc);
        __syncthreads();
        if (nb + 2 < 4) {
            uint32_t dst = (nb & 1) ? sB1 : sB0;
            fill_tile_async<256>(dst, Wh + (nb + 2) * 16384, tid);
            fill_tile_async<256>(dst + 32768, Wl + (nb + 2) * 16384, tid);
        }
        CP_COMMIT();
#pragma unroll
        for (int mi = 0; mi < 4; mi++)
#pragma unroll
            for (int ni = 0; ni < 4; ni++) {
                int r = wm * 64 + mi * 16 + (lane >> 2);
                int c = wn * 32 + ni * 8 + (lane & 3) * 2;
                *(__half2*)(dstb + (size_t)r * 512 + nb * 128 + c) =
                    __floats2half2_rn(acc[mi][ni][0], acc[mi][ni][1]);
                *(__half2*)(dstb + (size_t)(r + 8) * 512 + nb * 128 + c) =
                    __floats2half2_rn(acc[mi][ni][2], acc[mi][ni][3]);
            }
    }
}

// ---------------- attn / gat / final ----------------
__global__ void attn_kernel() {
    __shared__ float sc[16];
    const int tid = threadIdx.x, w = tid >> 5, lane = tid & 31;
    const int b = w >> 2, t = w & 3;
    float acc = 0.f;
    for (int g = lane; g < 1024; g += 32)
        acc += g_gf[(16 + b) * 1024 + g] * g_gf[(t * 4 + b) * 1024 + g];
#pragma unroll
    for (int o = 16; o; o >>= 1) acc += __shfl_xor_sync(0xffffffffu, acc, o);
    if (lane == 0) sc[b * 4 + t] = acc * (1.f / 32.f);
    __syncthreads();
    if (tid < 4) {
        int bb = tid;
        float m = sc[bb * 4];
        for (int i = 1; i < 4; i++) m = fmaxf(m, sc[bb * 4 + i]);
        float e[4], s = 0.f;
        for (int i = 0; i < 4; i++) { e[i] = expf(sc[bb * 4 + i] - m); s += e[i]; }
        for (int i = 0; i < 4; i++) g_attn[bb * 4 + i] = e[i] / s;
    }
}
__global__ __launch_bounds__(128) void gat_kernel(const float* __restrict__ att_w) {
    __shared__ __half xlsh[16 * 512];
    __shared__ float xrs[512], aws[512], es[64], as_[64];
    __shared__ int nb[16];
    const int tid = threadIdx.x, n = blockIdx.x, fr = blockIdx.y;
    const __half* XL = g_XLR + (size_t)4 * NPTS * 512;
    const __half* XR = g_XLR + (size_t)fr * NPTS * 512;
    {   // xr: 4 halfs per thread -> fp32 smem
        __half2 a = ((const __half2*)(XR + (size_t)n * 512))[tid * 2];
        __half2 b2_ = ((const __half2*)(XR + (size_t)n * 512))[tid * 2 + 1];
        float2 fa = __half22float2(a), fb = __half22float2(b2_);
        xrs[tid * 4] = fa.x; xrs[tid * 4 + 1] = fa.y;
        xrs[tid * 4 + 2] = fb.x; xrs[tid * 4 + 3] = fb.y;
    }
    *(float4*)&aws[tid * 4] = *(const float4*)(att_w + tid * 4);
    if (tid < 16) nb[tid] = g_nbr[((size_t)fr * NPTS + n) * KNB + tid];
    __syncthreads();
#pragma unroll
    for (int k = 0; k < 16; k++)     // gather fp16 rows: 8B per thread per row
        ((uint2*)&xlsh[k * 512])[tid] = ((const uint2*)(XL + (size_t)nb[k] * 512))[tid];
    __syncthreads();
    {
        const int pr = tid >> 1, hf = tid & 1;
        const int k = pr & 15, h = pr >> 4;
        float acc = 0.f;
#pragma unroll 4
        for (int c0 = 0; c0 < 64; c0++) {
            int c = hf * 64 + ((c0 + pr + hf * 16) & 63);
            float v = __half2float(xlsh[k * 512 + h * 128 + c]) + xrs[h * 128 + c];
            acc += aws[h * 128 + c] * (v < 0.f ? 0.2f * v : v);
        }
        acc += __shfl_xor_sync(0xffffffffu, acc, 1);
        if (!hf) es[h * 16 + k] = acc;
    }
    __syncthreads();
    if (tid < 4) {
        const int h = tid;
        float m = -1e30f;
        for (int k = 0; k < 16; k++) m = fmaxf(m, es[h * 16 + k]);
        float ex[16], s = 0.f;
        for (int k = 0; k < 16; k++) { ex[k] = expf(es[h * 16 + k] - m); s += ex[k]; }
        for (int k = 0; k < 16; k++) as_[h * 16 + k] = ex[k] / s;
    }
    __syncthreads();
    float o = 0.f;
#pragma unroll
    for (int h = 0; h < 4; h++) {
        float oh = 0.f;
#pragma unroll
        for (int k = 0; k < 16; k++)
            oh += as_[h * 16 + k] * __half2float(xlsh[k * 512 + h * 128 + tid]);
        o += oh;
    }
    g_res[((size_t)fr * NPTS + n) * 128 + tid] = o * 0.25f;
}
__global__ __launch_bounds__(128) void final_kernel(const float* __restrict__ seq, float* __restrict__ out) {
    const int n = blockIdx.x, c = threadIdx.x, b = n >> 12;
    float w = 0.f;
#pragma unroll
    for (int i = 0; i < 4; i++)
        w += g_attn[b * 4 + i] * g_res[((size_t)i * NPTS + n) * 128 + c];
    const float* last = seq + (size_t)4 * NPTS * 128;
    out[(size_t)n * 256 + c] = last[(size_t)n * 128 + c];
    out[(size_t)n * 256 + 128 + c] = w;
}

// ---------------- launch (knn at my #4: ncu -s 5 captures it, per R9 evidence) ----------------
extern "C" void kernel_launch(void* const* d_in, const int* in_sizes, int n_in,
                              void* d_out, int out_size) {
    (void)in_sizes; (void)n_in; (void)out_size;
    const float* seq = (const float*)d_in[0];
    const float* W1  = (const float*)d_in[1];
    const float* b1  = (const float*)d_in[2];
    const float* W2  = (const float*)d_in[3];
    const float* b2  = (const float*)d_in[4];
    const float* Wl  = (const float*)d_in[5];
    const float* Wr  = (const float*)d_in[6];
    const float* aw  = (const float*)d_in[7];
    float* out = (float*)d_out;

    __half *pw1h, *pw1l, *pw2h, *pw2l, *pwlh, *pwll, *pwrh, *pwrl;
    cudaGetSymbolAddress((void**)&pw1h, g_w1h); cudaGetSymbolAddress((void**)&pw1l, g_w1l);
    cudaGetSymbolAddress((void**)&pw2h, g_w2h); cudaGetSymbolAddress((void**)&pw2l, g_w2l);
    cudaGetSymbolAddress((void**)&pwlh, g_wlh); cudaGetSymbolAddress((void**)&pwll, g_wll);
    cudaGetSymbolAddress((void**)&pwrh, g_wrh); cudaGetSymbolAddress((void**)&pwrl, g_wrl);

    cudaFuncSetAttribute(gf_kernel,  cudaFuncAttributeMaxDynamicSharedMemorySize, GFSM);
    cudaFuncSetAttribute(xlr_kernel, cudaFuncAttributeMaxDynamicSharedMemorySize, XLSM);
    cudaFuncSetAttribute(knn_kernel, cudaFuncAttributeMaxDynamicSharedMemorySize, KNSM);

    zero_gf_kernel<<<80, 256>>>();                               // 1
    split_seq_kernel<<<10240, 256>>>(seq);                       // 2
    norm_kernel<<<512, 128>>>(seq);                              // 3
    knn_kernel<<<dim3(32, 4, 4), 512, KNSM>>>(seq);              // 4 <- ncu target
    tsplit_kernel<<<dim3(4, 4),  dim3(32, 8)>>>(W1, pw1h, pw1l, 128);
    tsplit_kernel<<<dim3(32, 4), dim3(32, 8)>>>(W2, pw2h, pw2l, 1024);
    tsplit_kernel<<<dim3(16, 4), dim3(32, 8)>>>(Wl, pwlh, pwll, 512);
    tsplit_kernel<<<dim3(16, 4), dim3(32, 8)>>>(Wr, pwrh, pwrl, 512);
    gf_kernel<<<640, 256, GFSM>>>(b1, b2);
    attn_kernel<<<1, 512>>>();
    xlr_kernel<<<dim3(128, 5), 256, XLSM>>>();
    gat_kernel<<<dim3(NPTS, 4), 128>>>(aw);
    final_kernel<<<NPTS, 128>>>(seq, out);
}